// round 5
// baseline (speedup 1.0000x reference)
#include <cuda_runtime.h>

// out_i = sign(x) * u_i / ||u||, u = W[0,1:4]; 0 when x == 0.
// 256-bit memory ops (sm_103a): input pinned in L2 via evict_last so
// back-to-back graph replays re-read it from L2; output streamed (.cs)
// so the 48MB write stream doesn't evict the 16MB input.

#define HWPIX (512 * 512)            // 2^18 elements per plane
#define NBATCH 16
#define ITERS 2                      // 8 floats per iter per thread
#define THREADS 256
#define BLOCK_ELEMS (THREADS * ITERS * 8)   // 4096 elems per block

__device__ __forceinline__ void ld8_pin(const float* p, float f[8]) {
    unsigned long long a, b, c, d;
    asm volatile("ld.global.nc.L2::evict_last.v4.b64 {%0,%1,%2,%3}, [%4];"
                 : "=l"(a), "=l"(b), "=l"(c), "=l"(d) : "l"(p));
    f[0] = __uint_as_float((unsigned)a); f[1] = __uint_as_float((unsigned)(a >> 32));
    f[2] = __uint_as_float((unsigned)b); f[3] = __uint_as_float((unsigned)(b >> 32));
    f[4] = __uint_as_float((unsigned)c); f[5] = __uint_as_float((unsigned)(c >> 32));
    f[6] = __uint_as_float((unsigned)d); f[7] = __uint_as_float((unsigned)(d >> 32));
}

__device__ __forceinline__ unsigned long long pack2(float lo, float hi) {
    return (unsigned long long)__float_as_uint(lo)
         | ((unsigned long long)__float_as_uint(hi) << 32);
}

__device__ __forceinline__ void st8_cs(float* p, const float f[8]) {
    unsigned long long a = pack2(f[0], f[1]);
    unsigned long long b = pack2(f[2], f[3]);
    unsigned long long c = pack2(f[4], f[5]);
    unsigned long long d = pack2(f[6], f[7]);
    asm volatile("st.global.cs.v4.b64 [%0], {%1,%2,%3,%4};"
                 :: "l"(p), "l"(a), "l"(b), "l"(c), "l"(d) : "memory");
}

__global__ __launch_bounds__(THREADS) void scene_normal_kernel(
    const float* __restrict__ depth,    // [16*512*512]
    const float* __restrict__ Wm,       // [8,8] row-major
    float* __restrict__ out)            // [16,3,512,512] flat
{
    const float u1 = Wm[1];
    const float u2 = Wm[2];
    const float u3 = Wm[3];
    const float r  = rsqrtf(u1 * u1 + u2 * u2 + u3 * u3);
    const float c1 = u1 * r, c2 = u2 * r, c3 = u3 * r;

    const int n0   = blockIdx.x * BLOCK_ELEMS;     // block-contiguous chunk
    const int b    = n0 >> 18;                     // HWPIX | BLOCK_ELEMS*64
    const int rem0 = n0 & (HWPIX - 1);

    const float* p  = depth + n0 + threadIdx.x * 8;
    float* basep    = out + (size_t)b * 3 * HWPIX + rem0 + threadIdx.x * 8;

#pragma unroll
    for (int i = 0; i < ITERS; i++) {
        const int off = i * THREADS * 8;
        float x[8];
        ld8_pin(p + off, x);

        float s[8], o[8];
#pragma unroll
        for (int j = 0; j < 8; j++)
            s[j] = (x[j] > 0.f) ? 1.f : ((x[j] < 0.f) ? -1.f : 0.f);

#pragma unroll
        for (int j = 0; j < 8; j++) o[j] = s[j] * c1;
        st8_cs(basep + off, o);
#pragma unroll
        for (int j = 0; j < 8; j++) o[j] = s[j] * c2;
        st8_cs(basep + HWPIX + off, o);
#pragma unroll
        for (int j = 0; j < 8; j++) o[j] = s[j] * c3;
        st8_cs(basep + 2 * HWPIX + off, o);
    }
}

extern "C" void kernel_launch(void* const* d_in, const int* in_sizes, int n_in,
                              void* d_out, int out_size)
{
    const float* depth = (const float*)d_in[0];
    const float* Wm    = (const float*)d_in[1];
    float* out         = (float*)d_out;

    const int n_elems = NBATCH * HWPIX;          // 4,194,304
    const int blocks  = n_elems / BLOCK_ELEMS;   // 1024

    scene_normal_kernel<<<blocks, THREADS>>>(depth, Wm, out);
}

// round 6
// speedup vs baseline: 1.0175x; 1.0175x over previous
#include <cuda_runtime.h>
#include <cstdint>

// out_i = sign(x) * u_i / ||u||, u = W[0,1:4]; 0 when x == 0.
// All bulk memory traffic moved off the per-thread LDG/STG path onto the
// TMA/bulk-copy engine: cp.async.bulk global->smem for the input tile,
// compute in SMEM, cp.async.bulk smem->global for the 3 output planes.

#define HWPIX (512 * 512)        // 2^18 elements per plane
#define NBATCH 16
#define TILE 2048                // elements per block (8KB)
#define THREADS 256
#define TILE_BYTES (TILE * 4)

__global__ __launch_bounds__(THREADS) void scene_normal_kernel(
    const float* __restrict__ depth,    // [16*512*512]
    const float* __restrict__ Wm,       // [8,8] row-major
    float* __restrict__ out)            // [16,3,512,512] flat
{
    __shared__ alignas(128) float s_in[TILE];
    __shared__ alignas(128) float s_out[3][TILE];
    __shared__ alignas(8) unsigned long long mbar;

    const int tid  = threadIdx.x;
    const int n0   = blockIdx.x * TILE;        // block-contiguous chunk
    const int b    = n0 >> 18;                 // TILE divides HWPIX
    const int rem0 = n0 & (HWPIX - 1);

    const uint32_t mbar_a = (uint32_t)__cvta_generic_to_shared(&mbar);
    const uint32_t sin_a  = (uint32_t)__cvta_generic_to_shared(s_in);

    if (tid == 0) {
        asm volatile("mbarrier.init.shared.b64 [%0], 1;" :: "r"(mbar_a) : "memory");
    }
    __syncthreads();

    if (tid == 0) {
        asm volatile("mbarrier.arrive.expect_tx.shared.b64 _, [%0], %1;"
                     :: "r"(mbar_a), "r"(TILE_BYTES) : "memory");
        asm volatile(
            "cp.async.bulk.shared::cluster.global.mbarrier::complete_tx::bytes "
            "[%0], [%1], %2, [%3];"
            :: "r"(sin_a), "l"(depth + n0), "r"(TILE_BYTES), "r"(mbar_a)
            : "memory");
    }

    // Constants computed while the bulk load is in flight.
    const float u1 = Wm[1];
    const float u2 = Wm[2];
    const float u3 = Wm[3];
    const float r  = rsqrtf(u1 * u1 + u2 * u2 + u3 * u3);
    const float c1 = u1 * r, c2 = u2 * r, c3 = u3 * r;

    // Wait for the input tile (phase 0, acquire).
    {
        uint32_t done;
        asm volatile(
            "{\n\t.reg .pred p;\n\t"
            "mbarrier.try_wait.parity.acquire.cta.shared::cta.b64 p, [%1], 0;\n\t"
            "selp.b32 %0, 1, 0, p;\n\t}"
            : "=r"(done) : "r"(mbar_a) : "memory");
        if (!done) {
            asm volatile(
                "{\n\t.reg .pred P1;\n\t"
                "WAIT_LOOP_%=:\n\t"
                "mbarrier.try_wait.parity.acquire.cta.shared::cta.b64 P1, [%0], 0, 0x989680;\n\t"
                "@P1 bra.uni WAIT_DONE_%=;\n\t"
                "bra.uni WAIT_LOOP_%=;\n\t"
                "WAIT_DONE_%=:\n\t}"
                :: "r"(mbar_a) : "memory");
        }
    }

    // Compute: TILE/4 = 512 float4s, 256 threads -> 2 per thread.
    const float4* in4 = reinterpret_cast<const float4*>(s_in);
    float4* o0 = reinterpret_cast<float4*>(s_out[0]);
    float4* o1 = reinterpret_cast<float4*>(s_out[1]);
    float4* o2 = reinterpret_cast<float4*>(s_out[2]);
#pragma unroll
    for (int i = 0; i < TILE / 4 / THREADS; i++) {
        const int idx = tid + i * THREADS;
        const float4 x = in4[idx];
        const float s0 = (x.x > 0.f) ? 1.f : ((x.x < 0.f) ? -1.f : 0.f);
        const float s1 = (x.y > 0.f) ? 1.f : ((x.y < 0.f) ? -1.f : 0.f);
        const float s2 = (x.z > 0.f) ? 1.f : ((x.z < 0.f) ? -1.f : 0.f);
        const float s3 = (x.w > 0.f) ? 1.f : ((x.w < 0.f) ? -1.f : 0.f);
        o0[idx] = make_float4(s0 * c1, s1 * c1, s2 * c1, s3 * c1);
        o1[idx] = make_float4(s0 * c2, s1 * c2, s2 * c2, s3 * c2);
        o2[idx] = make_float4(s0 * c3, s1 * c3, s2 * c3, s3 * c3);
    }
    __syncthreads();
    asm volatile("fence.proxy.async.shared::cta;" ::: "memory");

    if (tid == 0) {
        float* dst = out + (size_t)b * 3 * HWPIX + rem0;
#pragma unroll
        for (int pln = 0; pln < 3; pln++) {
            const uint32_t so = (uint32_t)__cvta_generic_to_shared(s_out[pln]);
            asm volatile(
                "cp.async.bulk.global.shared::cta.bulk_group [%0], [%1], %2;"
                :: "l"(dst + pln * HWPIX), "r"(so), "r"(TILE_BYTES)
                : "memory");
        }
        asm volatile("cp.async.bulk.commit_group;" ::: "memory");
        asm volatile("cp.async.bulk.wait_group 0;" ::: "memory");
    }
}

extern "C" void kernel_launch(void* const* d_in, const int* in_sizes, int n_in,
                              void* d_out, int out_size)
{
    const float* depth = (const float*)d_in[0];
    const float* Wm    = (const float*)d_in[1];
    float* out         = (float*)d_out;

    const int n_elems = NBATCH * HWPIX;      // 4,194,304
    const int blocks  = n_elems / TILE;      // 2048

    scene_normal_kernel<<<blocks, THREADS>>>(depth, Wm, out);
}